// round 9
// baseline (speedup 1.0000x reference)
#include <cuda_runtime.h>
#include <cuda_fp16.h>
#include <cstdint>
#include <cstddef>

// m16n8k16 row.col f32.f16.f16.f32 (family-common PTX, works on plain sm_103)
#define MMA_F16(c, a, b0, b1)                                                   \
    asm volatile("mma.sync.aligned.m16n8k16.row.col.f32.f16.f16.f32 "           \
                 "{%0,%1,%2,%3},{%4,%5,%6,%7},{%8,%9},{%0,%1,%2,%3};"           \
                 : "+f"((c)[0]), "+f"((c)[1]), "+f"((c)[2]), "+f"((c)[3])       \
                 : "r"((a)[0]), "r"((a)[1]), "r"((a)[2]), "r"((a)[3]),          \
                   "r"(b0), "r"(b1))

// ---------------- problem constants ----------------
static constexpr int BATCH = 16;
static constexpr int C     = 64;     // CIN == COUT
static constexpr int HW    = 112;
static constexpr int TH    = 8;      // tile h  -> M = 128 pixels per CTA
static constexpr int TW    = 16;     // tile w

// halo layout: [s(4)][row(10)][w(18)][pair-slot(8)] of half2 words
//   slot pp = logical p' XOR 2*((w>>2)&3); p' = 2t <-> cin pair (16s+2t, +1),
//   p' = 2t+1 <-> cin pair (16s+8+2t, +1). LDS.64 at even pp gives both K-halves.
static constexpr int ROW_W   = 18 * 8;        // 144 words per row
static constexpr int SLICE_W = 10 * ROW_W;    // 1440 words per s-slice

// fragment-ordered fp16 weights: 288 chunks x 512 B = 73728 B
__device__ uint32_t g_B2[36864];

// ---- prep kernel: wt[fp32, (cin*9+kpos) x 64] -> fragment-ordered fp16 pairs ----
__global__ void __launch_bounds__(256, 1)
prep_weights(const float* __restrict__ wt)
{
    int idx    = blockIdx.x * 256 + threadIdx.x;   // 0..36863
    int chunk  = idx >> 7;
    int within = idx & 127;
    int lane = within >> 2, r = within & 3;
    int h2   = chunk & 1;
    int wn   = (chunk >> 1) & 1;
    int s    = (chunk >> 2) & 3;
    int kpos = chunk >> 4;                          // 0..8
    int nt   = h2 * 2 + (r >> 1);
    int breg = r & 1;
    int g = lane >> 2, t = lane & 3;
    int co  = wn * 32 + nt * 8 + g;
    int cin = s * 16 + 2 * t + breg * 8;
    __half lo = __float2half_rn(wt[((size_t)cin * 9 + kpos) * 64 + co]);
    __half hi = __float2half_rn(wt[((size_t)(cin + 1) * 9 + kpos) * 64 + co]);
    __half2 v = __halves2half2(lo, hi);
    g_B2[idx] = *(uint32_t*)&v;
}

__global__ void __launch_bounds__(256, 4)
conv3x3_f16_mma(const float* __restrict__ x,
                const float* __restrict__ bias,
                float* __restrict__ out)
{
    __shared__ uint32_t halo[4 * SLICE_W];          // 5760 words = 23040 B

    const int tid  = threadIdx.x;
    const int lane = tid & 31;
    const int wid  = tid >> 5;
    const int wm   = wid >> 1;          // 0..3 : 2 h-rows each
    const int wn   = wid & 1;           // 0..1 : 32 couts each
    const int g    = lane >> 2;         // groupID 0..7
    const int t    = lane & 3;          // thread-in-group

    const int w0 = blockIdx.x * TW;
    const int h0 = blockIdx.y * TH;
    const int b  = blockIdx.z;

    // ---- halo load: 180 threads own fixed (r,w), walk 64 channels, div-free ----
    if (tid < 180) {
        int r = tid / 18;
        int w = tid - r * 18;
        int gh = h0 - 1 + r, gw = w0 - 1 + w;
        bool ok = ((unsigned)gh < (unsigned)HW) && ((unsigned)gw < (unsigned)HW);
        const float* src = x + (((size_t)b * C) * HW + gh) * HW + gw;
        const int wb  = (r * 18 + w) * 8;
        const int swz = 2 * ((w >> 2) & 3);
        __half* hh = (__half*)halo;
        #pragma unroll 1
        for (int s = 0; s < 4; ++s) {
            #pragma unroll
            for (int cs = 0; cs < 16; ++cs) {
                int pair = cs >> 1;
                int pp = ((((pair & 3) << 1) | (pair >> 2))) ^ swz;
                float v = ok ? __ldg(src + (size_t)(s * 16 + cs) * HW * HW) : 0.f;
                hh[2 * (s * SLICE_W + wb + pp) + (cs & 1)] = __float2half_rn(v);
            }
        }
    }
    __syncthreads();

    float acc[2][4][4];                 // [mt][nt][creg]
    #pragma unroll
    for (int i = 0; i < 2; ++i)
        #pragma unroll
        for (int j = 0; j < 4; ++j)
            #pragma unroll
            for (int k = 0; k < 4; ++k) acc[i][j][k] = 0.f;

    // precomputed swizzled base pointers: [kw][h2] -> (w = g + kw + 8*h2, slot 2t^swz)
    const uint32_t* hb[3][2];
    #pragma unroll
    for (int kw = 0; kw < 3; ++kw)
        #pragma unroll
        for (int h2 = 0; h2 < 2; ++h2) {
            int w = g + kw + h2 * 8;
            int pp = (2 * t) ^ (2 * ((w >> 2) & 3));
            hb[kw][h2] = halo + (wm * 2) * ROW_W + w * 8 + pp;
        }

    const uint4* bq = (const uint4*)g_B2 + wn * 64 + lane;

    #pragma unroll
    for (int kpos = 0; kpos < 9; ++kpos) {
        const int kh = kpos / 3;
        const int kw = kpos % 3;
        #pragma unroll
        for (int s = 0; s < 4; ++s) {
            // A: 4 x LDS.64 (each = both K-half pairs for one pixel column)
            uint2 a0c0 = *(const uint2*)(hb[kw][0] + s * SLICE_W + kh * ROW_W);
            uint2 a0c1 = *(const uint2*)(hb[kw][1] + s * SLICE_W + kh * ROW_W);
            uint2 a1c0 = *(const uint2*)(hb[kw][0] + s * SLICE_W + (kh + 1) * ROW_W);
            uint2 a1c1 = *(const uint2*)(hb[kw][1] + s * SLICE_W + (kh + 1) * ROW_W);
            uint32_t Am[2][4] = {{a0c0.x, a0c1.x, a0c0.y, a0c1.y},
                                 {a1c0.x, a1c1.x, a1c0.y, a1c1.y}};
            // B: 2 x LDG.128 from L1-resident fragment-ordered weights
            uint4 Blo = __ldg(bq + (kpos * 4 + s) * 128);
            uint4 Bhi = __ldg(bq + (kpos * 4 + s) * 128 + 32);
            uint32_t Bf[8] = {Blo.x, Blo.y, Blo.z, Blo.w,
                              Bhi.x, Bhi.y, Bhi.z, Bhi.w};

            #pragma unroll
            for (int mt = 0; mt < 2; ++mt)
                #pragma unroll
                for (int nt = 0; nt < 4; ++nt)
                    MMA_F16(acc[mt][nt], Am[mt], Bf[2 * nt], Bf[2 * nt + 1]);
        }
    }

    // ---- epilogue ----
    #pragma unroll
    for (int nt = 0; nt < 4; ++nt) {
        const int co0 = wn * 32 + nt * 8 + 2 * t;
        const float bz0 = __ldg(bias + co0);
        const float bz1 = __ldg(bias + co0 + 1);
        #pragma unroll
        for (int mt = 0; mt < 2; ++mt) {
            const int h = h0 + wm * 2 + mt;
            float* p0 = out + (((size_t)b * C + co0) * HW + h) * HW + w0;
            float* p1 = p0 + (size_t)HW * HW;
            p0[g]     = acc[mt][nt][0] + bz0;   // w=g,   cout co0
            p1[g]     = acc[mt][nt][1] + bz1;   // w=g,   cout co0+1
            p0[g + 8] = acc[mt][nt][2] + bz0;   // w=g+8, cout co0
            p1[g + 8] = acc[mt][nt][3] + bz1;   // w=g+8, cout co0+1
        }
    }
}

extern "C" void kernel_launch(void* const* d_in, const int* in_sizes, int n_in,
                              void* d_out, int out_size)
{
    const float* x    = (const float*)d_in[0];
    const float* wt   = (const float*)d_in[1];
    const float* bias = (const float*)d_in[2];
    float* out = (float*)d_out;

    prep_weights<<<144, 256>>>(wt);     // 144*256 == 36864 exactly

    dim3 grid(HW / TW, HW / TH, BATCH);   // 7 x 14 x 16
    conv3x3_f16_mma<<<grid, 256>>>(x, bias, out);
}

// round 10
// speedup vs baseline: 1.0335x; 1.0335x over previous
#include <cuda_runtime.h>
#include <cuda_fp16.h>
#include <cstdint>
#include <cstddef>

// m16n8k16 row.col f32.f16.f16.f32 (family-common PTX, works on plain sm_103)
#define MMA_F16(c, a, b0, b1)                                                   \
    asm volatile("mma.sync.aligned.m16n8k16.row.col.f32.f16.f16.f32 "           \
                 "{%0,%1,%2,%3},{%4,%5,%6,%7},{%8,%9},{%0,%1,%2,%3};"           \
                 : "+f"((c)[0]), "+f"((c)[1]), "+f"((c)[2]), "+f"((c)[3])       \
                 : "r"((a)[0]), "r"((a)[1]), "r"((a)[2]), "r"((a)[3]),          \
                   "r"(b0), "r"(b1))

// ---------------- problem constants ----------------
static constexpr int BATCH = 16;
static constexpr int C     = 64;     // CIN == COUT
static constexpr int HW    = 112;
static constexpr int TH    = 16;     // tile h  -> M = 256 pixels per CTA
static constexpr int TW    = 16;     // tile w

// halo: 32 channel-pairs x 18 rows x 18 cols of half2 words
static constexpr int PRS   = 20;     // row stride in words (half2)
static constexpr int PPL   = 360;    // pair-plane stride in words; 360 % 32 == 8 -> conflict-free

// fragment-ordered fp16 weights: 288 chunks x 512 B = 73728 B
__device__ uint32_t g_B2[36864];

// ---- prep kernel: wt[fp32, (cin*9+kpos) x 64] -> fragment-ordered fp16 pairs ----
__global__ void __launch_bounds__(256, 1)
prep_weights(const float* __restrict__ wt)
{
    int idx    = blockIdx.x * 256 + threadIdx.x;   // 0..36863
    int chunk  = idx >> 7;
    int within = idx & 127;
    int lane = within >> 2, r = within & 3;
    int h2   = chunk & 1;
    int wn   = (chunk >> 1) & 1;
    int s    = (chunk >> 2) & 3;
    int kpos = chunk >> 4;                          // 0..8
    int nt   = h2 * 2 + (r >> 1);
    int breg = r & 1;
    int g = lane >> 2, t = lane & 3;
    int co  = wn * 32 + nt * 8 + g;
    int cin = s * 16 + 2 * t + breg * 8;
    __half lo = __float2half_rn(wt[((size_t)cin * 9 + kpos) * 64 + co]);
    __half hi = __float2half_rn(wt[((size_t)(cin + 1) * 9 + kpos) * 64 + co]);
    __half2 v = __halves2half2(lo, hi);
    g_B2[idx] = *(uint32_t*)&v;
}

__global__ void __launch_bounds__(256, 2)
conv3x3_f16_mma(const float* __restrict__ x,
                const float* __restrict__ bias,
                float* __restrict__ out)
{
    __shared__ uint32_t halo32[32 * PPL];           // 11520 words = 46080 B
    __half* haloh = (__half*)halo32;

    const int tid  = threadIdx.x;
    const int lane = tid & 31;
    const int wid  = tid >> 5;
    const int wm   = wid >> 1;          // 0..3 : 4 h-rows each
    const int wn   = wid & 1;           // 0..1 : 32 couts each
    const int g    = lane >> 2;         // groupID 0..7
    const int t    = lane & 3;          // thread-in-group

    const int w0 = blockIdx.x * TW;
    const int h0 = blockIdx.y * TH;
    const int b  = blockIdx.z;

    // ---- halo load: 64 cin x 18 x 18 -> fp16 channel-pair layout, zero padded ----
    #pragma unroll 4
    for (int i = 0; i < 81; ++i) {      // 81*256 == 64*18*18 exactly
        int idx = tid + i * 256;
        int c   = idx / 324;
        int rem = idx - c * 324;
        int r   = rem / 18;
        int w   = rem - r * 18;
        int gh = h0 - 1 + r, gw = w0 - 1 + w;
        float v = 0.f;
        if ((unsigned)gh < (unsigned)HW && (unsigned)gw < (unsigned)HW)
            v = x[(((size_t)b * C + c) * HW + gh) * HW + gw];
        haloh[(c >> 1) * (2 * PPL) + r * (2 * PRS) + 2 * w + (c & 1)] = __float2half_rn(v);
    }
    __syncthreads();

    float acc[4][4][4];                 // [mt][nt][creg]
    #pragma unroll
    for (int i = 0; i < 4; ++i)
        #pragma unroll
        for (int j = 0; j < 4; ++j)
            #pragma unroll
            for (int k = 0; k < 4; ++k) acc[i][j][k] = 0.f;

    #pragma unroll 1
    for (int kpos = 0; kpos < 9; ++kpos) {
        const int kh = kpos / 3;
        const int kw = kpos - kh * 3;

        // A base: pair = s*8 + t (+4), row = wm*4 + mt + kh, col = (g|g+8) + kw
        const uint32_t* aw = halo32 + t * PPL + (wm * 4 + kh) * PRS + g + kw;
        const uint4* bq = (const uint4*)g_B2 + (size_t)(kpos * 4) * 128 + wn * 64 + lane;

        #pragma unroll
        for (int s = 0; s < 4; ++s) {
            uint32_t A[4][4];
            #pragma unroll
            for (int mt = 0; mt < 4; ++mt) {
                const uint32_t* p = aw + s * 8 * PPL + mt * PRS;
                A[mt][0] = p[0];            // pair t,   w=g
                A[mt][1] = p[8];            // pair t,   w=g+8
                A[mt][2] = p[4 * PPL];      // pair t+4, w=g
                A[mt][3] = p[4 * PPL + 8];  // pair t+4, w=g+8
            }
            uint32_t Bf[8];
            *(uint4*)&Bf[0] = __ldg(bq + (size_t)s * 128);        // h2=0: nt0,nt1
            *(uint4*)&Bf[4] = __ldg(bq + (size_t)s * 128 + 32);   // h2=1: nt2,nt3

            #pragma unroll
            for (int mt = 0; mt < 4; ++mt)
                #pragma unroll
                for (int nt = 0; nt < 4; ++nt)
                    MMA_F16(acc[mt][nt], A[mt], Bf[2 * nt], Bf[2 * nt + 1]);
        }
    }

    // ---- epilogue ----
    #pragma unroll
    for (int nt = 0; nt < 4; ++nt) {
        const int co0 = wn * 32 + nt * 8 + 2 * t;
        const float bz0 = __ldg(bias + co0);
        const float bz1 = __ldg(bias + co0 + 1);
        #pragma unroll
        for (int mt = 0; mt < 4; ++mt) {
            const int h = h0 + wm * 4 + mt;
            float* p0 = out + (((size_t)b * C + co0) * HW + h) * HW + w0;
            float* p1 = p0 + (size_t)HW * HW;
            p0[g]     = acc[mt][nt][0] + bz0;   // w=g,   cout co0
            p1[g]     = acc[mt][nt][1] + bz1;   // w=g,   cout co0+1
            p0[g + 8] = acc[mt][nt][2] + bz0;   // w=g+8, cout co0
            p1[g + 8] = acc[mt][nt][3] + bz1;   // w=g+8, cout co0+1
        }
    }
}

extern "C" void kernel_launch(void* const* d_in, const int* in_sizes, int n_in,
                              void* d_out, int out_size)
{
    const float* x    = (const float*)d_in[0];
    const float* wt   = (const float*)d_in[1];
    const float* bias = (const float*)d_in[2];
    float* out = (float*)d_out;

    prep_weights<<<144, 256>>>(wt);     // 144*256 == 36864 exactly

    dim3 grid(HW / TW, HW / TH, BATCH);   // 7 x 7 x 16
    conv3x3_f16_mma<<<grid, 256>>>(x, bias, out);
}

// round 11
// speedup vs baseline: 1.5901x; 1.5386x over previous
#include <cuda_runtime.h>
#include <cuda_fp16.h>
#include <cstdint>
#include <cstddef>

// m16n8k16 row.col f32.f16.f16.f32 (family-common PTX, works on plain sm_103)
#define MMA_F16(c, a, b0, b1)                                                   \
    asm volatile("mma.sync.aligned.m16n8k16.row.col.f32.f16.f16.f32 "           \
                 "{%0,%1,%2,%3},{%4,%5,%6,%7},{%8,%9},{%0,%1,%2,%3};"           \
                 : "+f"((c)[0]), "+f"((c)[1]), "+f"((c)[2]), "+f"((c)[3])       \
                 : "r"((a)[0]), "r"((a)[1]), "r"((a)[2]), "r"((a)[3]),          \
                   "r"(b0), "r"(b1))

// ---------------- problem constants ----------------
static constexpr int BATCH = 16;
static constexpr int C     = 64;     // CIN == COUT
static constexpr int HW    = 112;
static constexpr int TH    = 8;      // tile h  -> M = 128 pixels per CTA
static constexpr int TW    = 16;     // tile w

// halo: 32 channel-pairs x 10 rows x 18 cols of half2 words
static constexpr int PRS   = 20;     // row stride in words (half2)
static constexpr int PPL   = 200;    // pair-plane stride in words; 200 % 32 == 8 -> conflict-free

// fragment-ordered fp16 weights: 288 chunks x 512 B = 73728 B
__device__ uint32_t g_B2[36864];

// ---- prep kernel: wt[fp32, (cin*9+kpos) x 64] -> fragment-ordered fp16 pairs ----
__global__ void __launch_bounds__(256, 1)
prep_weights(const float* __restrict__ wt)
{
    int idx    = blockIdx.x * 256 + threadIdx.x;   // 0..36863
    int chunk  = idx >> 7;
    int within = idx & 127;
    int lane = within >> 2, r = within & 3;
    int h2   = chunk & 1;
    int wn   = (chunk >> 1) & 1;
    int s    = (chunk >> 2) & 3;
    int kpos = chunk >> 4;                          // 0..8
    int nt   = h2 * 2 + (r >> 1);
    int breg = r & 1;
    int g = lane >> 2, t = lane & 3;
    int co  = wn * 32 + nt * 8 + g;
    int cin = s * 16 + 2 * t + breg * 8;
    __half lo = __float2half_rn(wt[((size_t)cin * 9 + kpos) * 64 + co]);
    __half hi = __float2half_rn(wt[((size_t)(cin + 1) * 9 + kpos) * 64 + co]);
    __half2 v = __halves2half2(lo, hi);
    g_B2[idx] = *(uint32_t*)&v;
}

__global__ void __launch_bounds__(256, 3)
conv3x3_f16_mma(const float* __restrict__ x,
                const float* __restrict__ bias,
                float* __restrict__ out)
{
    __shared__ uint32_t halo32[32 * PPL];           // 6400 words = 25600 B
    __half* haloh = (__half*)halo32;

    const int tid  = threadIdx.x;
    const int lane = tid & 31;
    const int wid  = tid >> 5;
    const int wm   = wid >> 1;          // 0..3 : 2 h-rows each
    const int wn   = wid & 1;           // 0..1 : 32 couts each
    const int g    = lane >> 2;         // groupID 0..7
    const int t    = lane & 3;          // thread-in-group

    const int w0 = blockIdx.x * TW;
    const int h0 = blockIdx.y * TH;
    const int b  = blockIdx.z;

    // ---- halo load: 64 cin x 10 x 18 -> fp16 channel-pair layout, zero padded ----
    #pragma unroll 5
    for (int i = 0; i < 45; ++i) {      // 45*256 == 64*10*18 exactly
        int idx = tid + i * 256;
        int c   = idx / 180;
        int rem = idx - c * 180;
        int r   = rem / 18;
        int w   = rem - r * 18;
        int gh = h0 - 1 + r, gw = w0 - 1 + w;
        float v = 0.f;
        if ((unsigned)gh < (unsigned)HW && (unsigned)gw < (unsigned)HW)
            v = x[(((size_t)b * C + c) * HW + gh) * HW + gw];
        haloh[(c >> 1) * (2 * PPL) + r * (2 * PRS) + 2 * w + (c & 1)] = __float2half_rn(v);
    }
    __syncthreads();

    float acc[2][4][4];                 // [mt][nt][creg]
    #pragma unroll
    for (int i = 0; i < 2; ++i)
        #pragma unroll
        for (int j = 0; j < 4; ++j)
            #pragma unroll
            for (int k = 0; k < 4; ++k) acc[i][j][k] = 0.f;

    const uint4* bq = (const uint4*)g_B2 + wn * 64 + lane;

    // loop order: s (outer, rolled) -> kw -> kh; A rows (wm*2 + mt + kh) factored:
    // only 4 row-fragments A[0..3] per (s,kw), reused by acc[mt] += A[mt+kh] * B[kh]
    #pragma unroll 1
    for (int s = 0; s < 4; ++s) {
        const uint32_t* aw = halo32 + t * PPL + (wm * 2) * PRS + g + s * 8 * PPL;
        const uint4*    bqs = bq + s * 128;

        #pragma unroll
        for (int kw = 0; kw < 3; ++kw) {
            const uint32_t* p = aw + kw;
            // A[d]: halo row wm*2 + d (d = mt + kh), both w-halves, both K-half pairs
            uint32_t A[4][4];
            #pragma unroll
            for (int d = 0; d < 4; ++d) {
                A[d][0] = p[d * PRS];                // pair t,   w=g
                A[d][1] = p[d * PRS + 8];            // pair t,   w=g+8
                A[d][2] = p[d * PRS + 4 * PPL];      // pair t+4, w=g
                A[d][3] = p[d * PRS + 4 * PPL + 8];  // pair t+4, w=g+8
            }
            #pragma unroll
            for (int kh = 0; kh < 3; ++kh) {
                const int kpos = kh * 3 + kw;
                uint32_t Bf[8];
                *(uint4*)&Bf[0] = __ldg(bqs + kpos * 512);        // h2=0: nt0,nt1
                *(uint4*)&Bf[4] = __ldg(bqs + kpos * 512 + 32);   // h2=1: nt2,nt3

                #pragma unroll
                for (int mt = 0; mt < 2; ++mt)
                    #pragma unroll
                    for (int nt = 0; nt < 4; ++nt)
                        MMA_F16(acc[mt][nt], A[mt + kh], Bf[2 * nt], Bf[2 * nt + 1]);
            }
        }
    }

    // ---- epilogue ----
    #pragma unroll
    for (int nt = 0; nt < 4; ++nt) {
        const int co0 = wn * 32 + nt * 8 + 2 * t;
        const float bz0 = __ldg(bias + co0);
        const float bz1 = __ldg(bias + co0 + 1);
        #pragma unroll
        for (int mt = 0; mt < 2; ++mt) {
            const int h = h0 + wm * 2 + mt;
            float* p0 = out + (((size_t)b * C + co0) * HW + h) * HW + w0;
            float* p1 = p0 + (size_t)HW * HW;
            p0[g]     = acc[mt][nt][0] + bz0;   // w=g,   cout co0
            p1[g]     = acc[mt][nt][1] + bz1;   // w=g,   cout co0+1
            p0[g + 8] = acc[mt][nt][2] + bz0;   // w=g+8, cout co0
            p1[g + 8] = acc[mt][nt][3] + bz1;   // w=g+8, cout co0+1
        }
    }
}

extern "C" void kernel_launch(void* const* d_in, const int* in_sizes, int n_in,
                              void* d_out, int out_size)
{
    const float* x    = (const float*)d_in[0];
    const float* wt   = (const float*)d_in[1];
    const float* bias = (const float*)d_in[2];
    float* out = (float*)d_out;

    prep_weights<<<144, 256>>>(wt);     // 144*256 == 36864 exactly

    dim3 grid(HW / TW, HW / TH, BATCH);   // 7 x 14 x 16
    conv3x3_f16_mma<<<grid, 256>>>(x, bias, out);
}